// round 1
// baseline (speedup 1.0000x reference)
#include <cuda_runtime.h>

#define DD 64
#define HH 128
#define WW 128
#define NVOX (DD*HH*WW)

// ---- iteration state (static device scratch; no allocations) ----
__device__ float g_buf0[NVOX];
__device__ float g_buf1[NVOX];
__device__ float g_du[NVOX];

// ---- compile-time constants (double-precision folded) ----
// spatial Gaussian blur taps: exp(-o^2/2)/sum, o=-2..2, sigma=1
__host__ __device__ constexpr double c_E05 = 0.60653065971263342426;  // exp(-0.5)
__host__ __device__ constexpr double c_E2  = 0.13533528323661269189;  // exp(-2)
__host__ __device__ constexpr double c_KS  = 1.0 + 2.0*c_E05 + 2.0*c_E2;
#define K0F ((float)(1.0   / c_KS))
#define K1F ((float)(c_E05 / c_KS))
#define K2F ((float)(c_E2  / c_KS))
// bilateral spatial constants exp(-d2/(2*1.5^2)), d2 = 0..3
#define SC0 1.0f
#define SC1 0.80073740291680056f
#define SC2 0.64118038842995463f
#define SC3 0.51341711903259202f

#define LOG_SQRT_2PI 0.91893853320467274178f

__device__ __forceinline__ float sigmoidf_fast(float x) {
    return __fdividef(1.0f, 1.0f + __expf(-x));
}

// du = (h1-h0)*(f1 - w0 - logprob), d0 = h1 - h0
__global__ void init_kernel(const float* __restrict__ img,
                            const float* __restrict__ h,
                            const float* __restrict__ f1,
                            const float* __restrict__ w0) {
    int i = blockIdx.x * blockDim.x + threadIdx.x;
    if (i >= NVOX) return;
    float h0 = h[i];
    float h1 = h[NVOX + i];
    float I  = img[i];
    float logp = -0.5f * I * I - LOG_SQRT_2PI;
    g_du[i]   = (h1 - h0) * (f1[i] - w0[0] - logp);
    g_buf0[i] = h1 - h0;
}

// missing-tap mass for blur-of-ones along one axis
__device__ __forceinline__ float axis_sum(int i, int N) {
    float m = 0.f;
    if (i == 0) m += K1F + K2F; else if (i == 1) m += K2F;
    int j = N - 1 - i;
    if (j == 0) m += K1F + K2F; else if (j == 1) m += K2F;
    return 1.f - m;
}

__global__ void __launch_bounds__(512)
iter_kernel(int flip,
            const float* __restrict__ img,
            const float* __restrict__ sw,
            const float* __restrict__ bw,
            const float* __restrict__ cm) {
    const float* __restrict__ dprev = flip ? g_buf1 : g_buf0;
    float*       __restrict__ dnext = flip ? g_buf0 : g_buf1;

    __shared__ float sq[12][12][12];   // sigmoid(d), zero-padded at volume edges
    __shared__ float si[12][12][12];   // image, zero-padded
    __shared__ float t1[12][12][8];    // x-blurred
    __shared__ float t2[12][8][8];     // xy-blurred

    const int tx = threadIdx.x, ty = threadIdx.y, tz = threadIdx.z;
    const int tid = tx + 8 * (ty + 8 * tz);
    const int x0 = blockIdx.x * 8, y0 = blockIdx.y * 8, z0 = blockIdx.z * 8;

    // cooperative halo load (12^3 = 1728 elems, 512 threads)
    float* sqf = &sq[0][0][0];
    float* sif = &si[0][0][0];
    #pragma unroll
    for (int e = tid; e < 12*12*12; e += 512) {
        int lz = e / 144;
        int r  = e - lz * 144;
        int ly = r / 12;
        int lx = r - ly * 12;
        int gz = z0 + lz - 2, gy = y0 + ly - 2, gx = x0 + lx - 2;
        float qv = 0.f, iv = 0.f;
        if ((unsigned)gz < DD && (unsigned)gy < HH && (unsigned)gx < WW) {
            int gi = (gz * HH + gy) * WW + gx;
            qv = sigmoidf_fast(dprev[gi]);
            iv = img[gi];
        }
        sqf[e] = qv;
        sif[e] = iv;
    }
    __syncthreads();

    // x-blur: t1[lz][ly][x'] over full zy halo (12*12*8 = 1152)
    #pragma unroll
    for (int e = tid; e < 12*12*8; e += 512) {
        int lz = e / 96;
        int r  = e - lz * 96;
        int ly = r / 8;
        int xx = r - ly * 8;
        const float* row = &sq[lz][ly][xx];
        t1[lz][ly][xx] = K2F * (row[0] + row[4]) + K1F * (row[1] + row[3]) + K0F * row[2];
    }
    __syncthreads();

    // y-blur: t2[lz][y'][x'] (12*8*8 = 768)
    #pragma unroll
    for (int e = tid; e < 12*8*8; e += 512) {
        int lz = e / 64;
        int r  = e - lz * 64;
        int yy = r / 8;
        int xx = r - yy * 8;
        t2[lz][yy][xx] = K2F * (t1[lz][yy][xx]   + t1[lz][yy+4][xx])
                       + K1F * (t1[lz][yy+1][xx] + t1[lz][yy+3][xx])
                       + K0F *  t1[lz][yy+2][xx];
    }
    __syncthreads();

    // z-blur: per-thread output voxel
    float sp1 = K2F * (t2[tz][ty][tx]   + t2[tz+4][ty][tx])
              + K1F * (t2[tz+1][ty][tx] + t2[tz+3][ty][tx])
              + K0F *  t2[tz+2][ty][tx];

    const int gz = z0 + tz, gy = y0 + ty, gx = x0 + tx;

    // bilateral: 27 taps, weights recomputed from image smem
    const float Ic = si[tz+2][ty+2][tx+2];
    float vz[3] = { gz > 0 ? 1.f : 0.f, 1.f, gz < DD-1 ? 1.f : 0.f };
    float vy[3] = { gy > 0 ? 1.f : 0.f, 1.f, gy < HH-1 ? 1.f : 0.f };
    float vx[3] = { gx > 0 ? 1.f : 0.f, 1.f, gx < WW-1 ? 1.f : 0.f };
    const float sc[4] = { SC0, SC1, SC2, SC3 };

    float den = 0.f, acc = 0.f, vs = 0.f;
    #pragma unroll
    for (int dz = -1; dz <= 1; dz++) {
        #pragma unroll
        for (int dy = -1; dy <= 1; dy++) {
            #pragma unroll
            for (int dx = -1; dx <= 1; dx++) {
                const int d2 = dz*dz + dy*dy + dx*dx;
                float In = si[tz+2+dz][ty+2+dy][tx+2+dx];
                float qn = sq[tz+2+dz][ty+2+dy][tx+2+dx];
                float df = Ic - In;
                float w  = sc[d2] * __expf(-2.f * df * df);
                den += w;
                acc += w * qn;
                vs  += w * (vz[dz+1] * vy[dy+1] * vx[dx+1]);
            }
        }
    }

    // label-mixing scalars (broadcast loads, folded per thread)
    float cm0 = cm[2] - cm[0];
    float cm1 = cm[3] - cm[1];
    float dA0 = cm0 * sw[0] + cm1 * sw[2];
    float dA1 = cm0 * sw[1] + cm1 * sw[3];
    float dB0 = cm0 * bw[0] + cm1 * bw[2];
    float dB1 = cm0 * bw[1] + cm1 * bw[3];

    // blur-of-ones (channel-0 reconstruction)
    float S = axis_sum(gz, DD) * axis_sum(gy, HH) * axis_sum(gx, WW);

    float pair = dA0 * S + (dA1 - dA0) * sp1
               + __fdividef(dB0 * vs + (dB1 - dB0) * acc, den);

    int gi = (gz * HH + gy) * WW + gx;
    dnext[gi] = g_du[gi] - pair;
}

__global__ void final_kernel(float* __restrict__ out,
                             const float* __restrict__ f1,
                             int src, int copy_f1) {
    int i = blockIdx.x * blockDim.x + threadIdx.x;
    if (i >= NVOX) return;
    const float* dsrc = src ? g_buf1 : g_buf0;
    float q = sigmoidf_fast(dsrc[i]);
    out[i]        = 1.f - q;   // channel 0
    out[NVOX + i] = q;         // channel 1
    if (copy_f1) out[2 * NVOX + i] = f1[i];
}

extern "C" void kernel_launch(void* const* d_in, const int* in_sizes, int n_in,
                              void* d_out, int out_size) {
    const float* img = (const float*)d_in[0];
    const float* h   = (const float*)d_in[1];
    const float* f1  = (const float*)d_in[2];
    const float* w0  = (const float*)d_in[3];
    const float* sw  = (const float*)d_in[4];
    const float* bw  = (const float*)d_in[5];
    const float* cm  = (const float*)d_in[6];
    float* out = (float*)d_out;

    init_kernel<<<(NVOX + 255) / 256, 256>>>(img, h, f1, w0);

    dim3 blk(8, 8, 8);
    dim3 grd(WW / 8, HH / 8, DD / 8);
    for (int it = 0; it < 5; it++) {
        iter_kernel<<<grd, blk>>>(it & 1, img, sw, bw, cm);
    }

    int copyf1 = (out_size >= 3 * NVOX) ? 1 : 0;
    final_kernel<<<(NVOX + 255) / 256, 256>>>(out, f1, 1 /* 5 iters end in buf1 */, copyf1);
}